// round 14
// baseline (speedup 1.0000x reference)
#include <cuda_runtime.h>
#include <cuda_bf16.h>

// Problem: x [64,224,224,32] f32; W_cls [32,4]; b_cls [4].
// out[b] = rot90(x[b], k[b]) with k[b] = argmax(mean_hw(x[b]) @ W + b).
//
// R14: WARP-level work queue. No __syncthreads anywhere in the task loop:
// each warp fetches tasks (lane0 atomic + shfl broadcast), reduces via
// xor-shuffles only, and rotate warps spin-wait individually. 256-px warp
// tasks = 64 loads/lane between fixed costs (R13 lesson: block barriers
// every 8 loads collapsed MLP; warp granularity removes the barriers).

#define BATCH 64
#define HW    224
#define PIX   (HW * HW)        // 50176
#define CH    32
#define SL    256              // pixels per warp task
#define SLICES (PIX / SL)      // 196 slices per image pass
#define DLY   16
#define NGROUP (2 * BATCH)     // 128 groups
#define TOTAL_TASKS (NGROUP * SLICES)   // 25088
#define GRID_BLOCKS (148 * 8)           // 1184 blocks = 9472 warps
#define TOTAL_WARPS (GRID_BLOCKS * 8)

// Queue state: zero-init at load, restored by last exiting warp.
__device__ float4   g_partial[BATCH * SLICES * 8];
__device__ int      g_k[BATCH];
__device__ unsigned g_ctr;
__device__ int      g_done[BATCH];
__device__ int      g_flag[BATCH];
__device__ unsigned g_exit;

// Gather affine coefficients (float4 units, before +q):
//   k=0: si=i,     sj=j      k=1: si=j,     sj=223-i
//   k=2: si=223-i, sj=223-j  k=3: si=223-j, sj=i
__constant__ int c_A[4] = { HW*8,      -8,      -HW*8,   8      };
__constant__ int c_B[4] = { 8,          HW*8,   -8,      -HW*8  };
__constant__ int c_C[4] = { 0,          223*8,  (223*HW+223)*8, 223*HW*8 };

__global__ void __launch_bounds__(256, 8) fused_kernel(const float4* __restrict__ x,
                                                       const float*  __restrict__ W_cls,
                                                       const float*  __restrict__ b_cls,
                                                       float4*       __restrict__ out) {
    const int lane = threadIdx.x & 31;
    const int q    = lane & 7;         // float4 slot within pixel
    const int p    = lane >> 3;        // pixel sub-index (0..3)
    const unsigned FULL = 0xffffffffu;

    for (;;) {
        int task;
        if (lane == 0) task = (int)atomicAdd(&g_ctr, 1u);
        task = __shfl_sync(FULL, task, 0);
        if (task >= TOTAL_TASKS) break;

        // -------- decode interleaved group schedule (delay = DLY) ---------
        const int g     = task / SLICES;
        const int slice = task - g * SLICES;
        int is_reduce, b;
        if (g < DLY)                 { is_reduce = 1; b = g; }
        else if (g < NGROUP - DLY)   { int h = g - DLY;
                                       is_reduce = !(h & 1);
                                       b = is_reduce ? (DLY + (h >> 1)) : (h >> 1); }
        else                         { is_reduce = 0;
                                       b = (BATCH - DLY) + (g - (NGROUP - DLY)); }

        if (is_reduce) {
            // ------- reduction warp-task: 256 px, 64 f4 loads per lane ----
            const unsigned base = ((unsigned)b * PIX + (unsigned)slice * SL) * 8u
                                  + (unsigned)(p * 8 + q);
            float4 s = make_float4(0.f, 0.f, 0.f, 0.f);
#pragma unroll 8
            for (int it = 0; it < 64; ++it) {
                float4 v = __ldg(&x[base + (unsigned)it * 32u]);
                s.x += v.x; s.y += v.y; s.z += v.z; s.w += v.w;
            }
            // combine lanes sharing q (differ in bits 3,4)
#pragma unroll
            for (int off = 8; off <= 16; off <<= 1) {
                s.x += __shfl_xor_sync(FULL, s.x, off);
                s.y += __shfl_xor_sync(FULL, s.y, off);
                s.z += __shfl_xor_sync(FULL, s.z, off);
                s.w += __shfl_xor_sync(FULL, s.w, off);
            }
            if (lane < 8)
                g_partial[(b * SLICES + slice) * 8 + lane] = s;
            __threadfence();

            int is_last = 0;
            if (lane == 0) {
                int old = atomicAdd(&g_done[b], 1);
                is_last = (old == SLICES - 1);
            }
            is_last = __shfl_sync(FULL, is_last, 0);

            if (is_last) {
                // in-warp: mean -> logits -> argmax (deterministic)
                if (lane == 0) __threadfence();
                __syncwarp(FULL);
                const int qq = lane >> 2, r = lane & 3;   // lane = channel
                float ssum = 0.f;
                for (int ch = 0; ch < SLICES; ++ch) {
                    float4 v = g_partial[(b * SLICES + ch) * 8 + qq];
                    ssum += (r == 0) ? v.x : (r == 1) ? v.y : (r == 2) ? v.z : v.w;
                }
                const float mean = ssum * (1.0f / (float)PIX);
                float4 w4 = __ldg(&((const float4*)W_cls)[lane]);  // W[c][0..3]
                float l0 = mean * w4.x, l1 = mean * w4.y,
                      l2 = mean * w4.z, l3 = mean * w4.w;
#pragma unroll
                for (int off = 16; off >= 1; off >>= 1) {
                    l0 += __shfl_xor_sync(FULL, l0, off);
                    l1 += __shfl_xor_sync(FULL, l1, off);
                    l2 += __shfl_xor_sync(FULL, l2, off);
                    l3 += __shfl_xor_sync(FULL, l3, off);
                }
                if (lane == 0) {
                    l0 += __ldg(&b_cls[0]); l1 += __ldg(&b_cls[1]);
                    l2 += __ldg(&b_cls[2]); l3 += __ldg(&b_cls[3]);
                    float best = l0; int bi = 0;                  // first-max
                    if (l1 > best) { best = l1; bi = 1; }
                    if (l2 > best) { best = l2; bi = 2; }
                    if (l3 > best) { best = l3; bi = 3; }
                    g_k[b] = bi;
                    __threadfence();
                    atomicExch(&g_flag[b], 1);
                }
            }
        } else {
            // ------- rotation warp-task: 256 px, gather -------------------
            int k;
            if (lane == 0) {
                while (0 == *(volatile int*)&g_flag[b]) __nanosleep(100);
                __threadfence();
                k = g_k[b];
            }
            k = __shfl_sync(FULL, k, 0);
            const int A = c_A[k], Bc = c_B[k];

            const float4* src_base = x   + (unsigned)b * PIX * 8u;
            float4*       out_base = out + (unsigned)b * PIX * 8u;

            int pix0 = slice * SL + p;
            int i = pix0 / HW;
            int j = pix0 - i * HW;
            int soff = A * i + Bc * j + c_C[k] + q;   // src float4 offset
            int doff = pix0 * 8 + q;                  // dst float4 offset
            const int stepB   = 4 * Bc;               // 4 pixels per iter
            const int wrapAdj = A - HW * Bc;

#pragma unroll 8
            for (int it = 0; it < 64; ++it) {
                float4 v = __ldg(&src_base[soff]);
                __stcs(&out_base[doff], v);
                doff += 4 * 8;
                j += 4; soff += stepB;
                if (j >= HW) { j -= HW; soff += wrapAdj; }
            }
        }
    }

    // ---- self-reset for next graph replay: last warp out cleans up -------
    if (lane == 0) {
        unsigned me = atomicAdd(&g_exit, 1u);
        if (me == TOTAL_WARPS - 1) {
            for (int i = 0; i < BATCH; ++i) { g_done[i] = 0; g_flag[i] = 0; }
            g_ctr  = 0u;
            g_exit = 0u;
            __threadfence();
        }
    }
}

extern "C" void kernel_launch(void* const* d_in, const int* in_sizes, int n_in,
                              void* d_out, int out_size) {
    const float4* x     = (const float4*)d_in[0];
    const float*  W_cls = (const float*)d_in[1];
    const float*  b_cls = (const float*)d_in[2];
    float4*       out   = (float4*)d_out;

    fused_kernel<<<GRID_BLOCKS, 256>>>(x, W_cls, b_cls, out);
}

// round 15
// speedup vs baseline: 2.6801x; 2.6801x over previous
#include <cuda_runtime.h>
#include <cuda_bf16.h>

// Problem: x [64,224,224,32] f32; W_cls [32,4]; b_cls [4].
// out[b] = rot90(x[b], k[b]) with k[b] = argmax(mean_hw(x[b]) @ W + b).
//
// R8 structure (proven best): persistent fused kernel, block-level atomic
// work queue, 1024-px tasks, reduce/rotate interleaved, grid 1184 (8/SM),
// last exiting block self-resets for graph replay.
// R15 changes: (1) DLY 6 -> 24 groups so the reduce->rotate handout delay
// (~37us) exceeds a reduce task's duration -- rotate blocks stop spinning
// on flag[b]; (2) rotate loop front-batches 4 independent LDG.128 before
// the 4 STG.128 (higher exposed MLP on the gather leg).

#define BATCH 64
#define HW    224
#define PIX   (HW * HW)        // 50176
#define CH    32
#define NCHUNK 49
#define DLY   24
#define NGROUP (2 * BATCH)                    // 128
#define TOTAL_TASKS (NGROUP * NCHUNK)         // 6272
#define GRID_BLOCKS (148 * 8)                 // 1184

// Queue state: zero-init at load, restored by last exiting block.
__device__ float4   g_partial[BATCH * NCHUNK * 8];
__device__ int      g_k[BATCH];
__device__ unsigned g_ctr;
__device__ int      g_done[BATCH];
__device__ int      g_flag[BATCH];
__device__ unsigned g_exit;

// Gather affine coefficients (float4 units, before +q):
//   k=0: si=i,     sj=j      k=1: si=j,     sj=223-i
//   k=2: si=223-i, sj=223-j  k=3: si=223-j, sj=i
__constant__ int c_A[4] = { HW*8,      -8,      -HW*8,   8      };
__constant__ int c_B[4] = { 8,          HW*8,   -8,      -HW*8  };
__constant__ int c_C[4] = { 0,          223*8,  (223*HW+223)*8, 223*HW*8 };

__global__ void __launch_bounds__(256, 8) fused_kernel(const float4* __restrict__ x,
                                                       const float*  __restrict__ W_cls,
                                                       const float*  __restrict__ b_cls,
                                                       float4*       __restrict__ out) {
    __shared__ float4 sm[8][8];
    __shared__ float  meanv[CH];
    __shared__ int    sh_task;
    __shared__ int    sh_last;
    __shared__ int    sh_k;

    const int t    = threadIdx.x;
    const int lane = t & 31;
    const int warp = t >> 5;
    const int q    = t & 7;

    for (;;) {
        __syncthreads();
        if (t == 0) sh_task = (int)atomicAdd(&g_ctr, 1u);
        __syncthreads();
        const int task = sh_task;
        if (task >= TOTAL_TASKS) break;

        // -------- decode interleaved schedule (delay = DLY groups) --------
        const int g     = task / NCHUNK;
        const int slice = task - g * NCHUNK;
        int is_reduce, b;
        if (g < DLY)                 { is_reduce = 1; b = g; }
        else if (g < NGROUP - DLY)   { int h = g - DLY;
                                       is_reduce = !(h & 1);
                                       b = is_reduce ? (DLY + (h >> 1)) : (h >> 1); }
        else                         { is_reduce = 0;
                                       b = (BATCH - DLY) + (g - (NGROUP - DLY)); }

        if (is_reduce) {
            // ---------------- reduction chunk (order-identical to R1) -------
            const unsigned base = ((unsigned)b * PIX + (unsigned)slice * 1024u) * 8u;

            float4 s = make_float4(0.f, 0.f, 0.f, 0.f);
#pragma unroll 4
            for (int it = 0; it < 32; ++it) {
                unsigned pix = (unsigned)(it * 32 + (t >> 3));
                float4 v = __ldg(&x[base + pix * 8u + q]);
                s.x += v.x; s.y += v.y; s.z += v.z; s.w += v.w;
            }
#pragma unroll
            for (int off = 8; off <= 16; off <<= 1) {
                s.x += __shfl_xor_sync(0xffffffffu, s.x, off);
                s.y += __shfl_xor_sync(0xffffffffu, s.y, off);
                s.z += __shfl_xor_sync(0xffffffffu, s.z, off);
                s.w += __shfl_xor_sync(0xffffffffu, s.w, off);
            }
            if (lane < 8) sm[warp][lane] = s;
            __syncthreads();

            if (t < 8) {
                float4 acc = sm[0][t];
#pragma unroll
                for (int w = 1; w < 8; ++w) {
                    float4 v = sm[w][t];
                    acc.x += v.x; acc.y += v.y; acc.z += v.z; acc.w += v.w;
                }
                g_partial[(b * NCHUNK + slice) * 8 + t] = acc;
                __threadfence();
            }
            __syncthreads();

            if (t == 0) {
                int old = atomicAdd(&g_done[b], 1);
                sh_last = (old == NCHUNK - 1);
            }
            __syncthreads();

            if (sh_last) {
                if (t == 0) __threadfence();
                __syncthreads();
                if (t < CH) {
                    const int qq = t >> 2, r = t & 3;
                    float ssum = 0.f;
                    for (int ch = 0; ch < NCHUNK; ++ch) {
                        float4 v = g_partial[(b * NCHUNK + ch) * 8 + qq];
                        ssum += (r == 0) ? v.x : (r == 1) ? v.y : (r == 2) ? v.z : v.w;
                    }
                    meanv[t] = ssum * (1.0f / (float)PIX);
                }
                __syncthreads();
                if (t == 0) {
                    float best = -3.402823466e38f;
                    int bi = 0;
#pragma unroll
                    for (int o = 0; o < 4; ++o) {
                        float l = __ldg(&b_cls[o]);
#pragma unroll
                        for (int cc = 0; cc < CH; ++cc)
                            l += meanv[cc] * __ldg(&W_cls[cc * 4 + o]);
                        if (l > best) { best = l; bi = o; }  // first-max (jnp.argmax)
                    }
                    g_k[b] = bi;
                    __threadfence();
                    atomicExch(&g_flag[b], 1);
                }
            }
        } else {
            // -------- rotation slice: gather, 4-wide front-batched loads ---
            if (t == 0) {
                while (0 == *(volatile int*)&g_flag[b]) __nanosleep(100);
                __threadfence();
                sh_k = g_k[b];
            }
            __syncthreads();
            const int k = sh_k;
            const int A = c_A[k], Bc = c_B[k];

            const float4* src_base = x   + (unsigned)b * PIX * 8u;
            float4*       out_base = out + (unsigned)b * PIX * 8u;

            int pix0 = slice * 1024 + (t >> 3);
            int i = pix0 / HW;
            int j = pix0 - i * HW;
            int soff = A * i + Bc * j + c_C[k] + q;   // src float4 offset
            int doff = pix0 * 8 + q;                  // dst float4 offset
            const int stepB   = 32 * Bc;
            const int wrapAdj = A - HW * Bc;

#pragma unroll
            for (int su = 0; su < 8; ++su) {
                // compute 4 gather offsets (32-px stride, wrap-corrected)
                int o0 = soff;
                j += 32; soff += stepB; if (j >= HW) { j -= HW; soff += wrapAdj; }
                int o1 = soff;
                j += 32; soff += stepB; if (j >= HW) { j -= HW; soff += wrapAdj; }
                int o2 = soff;
                j += 32; soff += stepB; if (j >= HW) { j -= HW; soff += wrapAdj; }
                int o3 = soff;
                j += 32; soff += stepB; if (j >= HW) { j -= HW; soff += wrapAdj; }
                // 4 independent loads, then 4 posted stores
                float4 v0 = __ldg(&src_base[o0]);
                float4 v1 = __ldg(&src_base[o1]);
                float4 v2 = __ldg(&src_base[o2]);
                float4 v3 = __ldg(&src_base[o3]);
                __stcs(&out_base[doff        ], v0);
                __stcs(&out_base[doff +  256 ], v1);
                __stcs(&out_base[doff +  512 ], v2);
                __stcs(&out_base[doff +  768 ], v3);
                doff += 1024;
            }
        }
    }

    // ---- self-reset for next graph replay: last block out cleans up ------
    __syncthreads();
    if (t == 0) {
        unsigned me = atomicAdd(&g_exit, 1u);
        if (me == GRID_BLOCKS - 1) {
            for (int i = 0; i < BATCH; ++i) { g_done[i] = 0; g_flag[i] = 0; }
            g_ctr  = 0u;
            g_exit = 0u;
            __threadfence();
        }
    }
}

extern "C" void kernel_launch(void* const* d_in, const int* in_sizes, int n_in,
                              void* d_out, int out_size) {
    const float4* x     = (const float4*)d_in[0];
    const float*  W_cls = (const float*)d_in[1];
    const float*  b_cls = (const float*)d_in[2];
    float4*       out   = (float4*)d_out;

    fused_kernel<<<GRID_BLOCKS, 256>>>(x, W_cls, b_cls, out);
}